// round 1
// baseline (speedup 1.0000x reference)
#include <cuda_runtime.h>

#define N_ENT  100000
#define DIM    128
#define R2     100
#define NBASES 4
#define NEDGE  400000
#define WCOLS  640   // 4*128 (bases) + 128 (root)

// ---- scratch (device globals; no allocation allowed) ----
__device__ __align__(16) int   g_counts[N_ENT * R2];              // 40 MB
__device__ __align__(16) float g_xb[(long long)N_ENT * 512];      // 204.8 MB
__device__ __align__(16) float g_h1[N_ENT * DIM];                 // 51.2 MB
__device__ __align__(16) float g_h2[N_ENT * DIM];                 // 51.2 MB
__device__ __align__(16) float g_wcat[DIM * WCOLS];               // 327 KB

// ---------------- norm precompute ----------------
__global__ void k_zero_counts() {
    int i = blockIdx.x * blockDim.x + threadIdx.x;
    if (i < N_ENT * R2) g_counts[i] = 0;
}

__global__ void k_hist(const int* __restrict__ dst, const int* __restrict__ et) {
    int e = blockIdx.x * blockDim.x + threadIdx.x;
    if (e < NEDGE) atomicAdd(&g_counts[dst[e] * R2 + et[e]], 1);
}

// ---------------- pack [bases | root] into one (128 x 640) weight ----------------
__global__ void k_build_w(const float* __restrict__ bases, const float* __restrict__ root) {
    int idx = blockIdx.x * blockDim.x + threadIdx.x;
    if (idx >= DIM * WCOLS) return;
    int d = idx / WCOLS;
    int c = idx % WCOLS;
    float v;
    if (c < 512) {
        int b = c >> 7, h = c & 127;
        v = bases[(b * DIM + d) * DIM + h];   // bases[b, d, h]
    } else {
        v = root[d * DIM + (c - 512)];        // root[d, h]
    }
    g_wcat[idx] = v;
}

// ---------------- fused GEMM:  act(X) @ Wcat -> (xb | agg+bias) ----------------
// MODE 0: act(x) = relu(x + inb[col]); input = X param;  agg = g_h1
// MODE 1: act(x) = relu(x);            input = g_h1;     agg = g_h2
// Tile: 128 rows x 64 cols per block, K chunk 32, 256 threads, 8x4 per thread.
// Accumulators kept as packed f32x2 pairs; fma.rn.f32x2 doubles fp32 FMA rate.
template<int MODE>
__global__ void __launch_bounds__(256) k_gemm(const float* __restrict__ Xp,
                                              const float* __restrict__ inb,
                                              const float* __restrict__ outb)
{
    __shared__ __align__(16) float As[32][132];  // [k][row], padded
    __shared__ __align__(16) float Ws[32][64];   // [k][col]
    const float* __restrict__ X = (MODE == 0) ? Xp : (const float*)g_h1;

    const int row0 = blockIdx.x * 128;
    const int col0 = blockIdx.y * 64;
    const int tid  = threadIdx.x;
    const int tx   = tid & 15;
    const int ty   = tid >> 4;

    unsigned long long acc[8][2];
#pragma unroll
    for (int r = 0; r < 8; r++) { acc[r][0] = 0ull; acc[r][1] = 0ull; }

    for (int kk = 0; kk < DIM; kk += 32) {
        __syncthreads();
        // load A tile (128 rows x 32 k), coalesced, apply input activation
#pragma unroll
        for (int i = 0; i < 16; i++) {
            int idx = tid + i * 256;
            int r = idx >> 5;
            int k = idx & 31;
            int gr = row0 + r;
            float v = 0.f;
            if (gr < N_ENT) {
                v = X[gr * DIM + kk + k];
                if (MODE == 0) v += inb[kk + k];
                v = fmaxf(v, 0.f);
            }
            As[k][r] = v;
        }
        // load W tile (32 k x 64 cols), coalesced
#pragma unroll
        for (int i = 0; i < 8; i++) {
            int idx = tid + i * 256;
            int k = idx >> 6;
            int c = idx & 63;
            Ws[k][c] = g_wcat[(kk + k) * WCOLS + col0 + c];
        }
        __syncthreads();
#pragma unroll
        for (int k = 0; k < 32; k++) {
            float4 a0 = *(const float4*)&As[k][8 * ty];
            float4 a1 = *(const float4*)&As[k][8 * ty + 4];
            ulonglong2 b = *(const ulonglong2*)&Ws[k][4 * tx];
            float av[8] = {a0.x, a0.y, a0.z, a0.w, a1.x, a1.y, a1.z, a1.w};
#pragma unroll
            for (int r = 0; r < 8; r++) {
                unsigned long long a2;
                asm("mov.b64 %0, {%1, %1};" : "=l"(a2) : "f"(av[r]));
                asm("fma.rn.f32x2 %0, %1, %2, %0;" : "+l"(acc[r][0]) : "l"(a2), "l"(b.x));
                asm("fma.rn.f32x2 %0, %1, %2, %0;" : "+l"(acc[r][1]) : "l"(a2), "l"(b.y));
            }
        }
    }

    float* agg = (MODE == 0) ? g_h1 : g_h2;
#pragma unroll
    for (int r = 0; r < 8; r++) {
        int gr = row0 + 8 * ty + r;
        if (gr >= N_ENT) continue;
        float o0, o1, o2, o3;
        asm("mov.b64 {%0, %1}, %2;" : "=f"(o0), "=f"(o1) : "l"(acc[r][0]));
        asm("mov.b64 {%0, %1}, %2;" : "=f"(o2), "=f"(o3) : "l"(acc[r][1]));
        int c = col0 + 4 * tx;
        if (col0 < 512) {
            *(float4*)&g_xb[(long long)gr * 512 + c] = make_float4(o0, o1, o2, o3);
        } else {
            int cc = c - 512;
            agg[gr * DIM + cc + 0] = o0 + outb[cc + 0];
            agg[gr * DIM + cc + 1] = o1 + outb[cc + 1];
            agg[gr * DIM + cc + 2] = o2 + outb[cc + 2];
            agg[gr * DIM + cc + 3] = o3 + outb[cc + 3];
        }
    }
}

// ---------------- edge pass: mix basis projections, scatter-add ----------------
// one warp per edge; lane owns 4 consecutive output features (float4)
template<int LAYER>
__global__ void __launch_bounds__(256) k_edge(const int* __restrict__ src,
                                              const int* __restrict__ dst,
                                              const int* __restrict__ et,
                                              const float* __restrict__ comp)
{
    int e = (blockIdx.x * blockDim.x + threadIdx.x) >> 5;
    int lane = threadIdx.x & 31;
    if (e >= NEDGE) return;
    int s = src[e];
    int d = dst[e];
    int t = et[e];
    float norm = 1.0f / fmaxf((float)g_counts[d * R2 + t], 1.0f);
    float c0 = comp[t * 4 + 0] * norm;
    float c1 = comp[t * 4 + 1] * norm;
    float c2 = comp[t * 4 + 2] * norm;
    float c3 = comp[t * 4 + 3] * norm;
    const float4* xb = (const float4*)(g_xb + (long long)s * 512);
    float4 v0 = xb[lane];
    float4 v1 = xb[32 + lane];
    float4 v2 = xb[64 + lane];
    float4 v3 = xb[96 + lane];
    float mx = c0 * v0.x + c1 * v1.x + c2 * v2.x + c3 * v3.x;
    float my = c0 * v0.y + c1 * v1.y + c2 * v2.y + c3 * v3.y;
    float mz = c0 * v0.z + c1 * v1.z + c2 * v2.z + c3 * v3.z;
    float mw = c0 * v0.w + c1 * v1.w + c2 * v2.w + c3 * v3.w;
    float* agg = (LAYER == 0) ? g_h1 : g_h2;
    float* p = agg + d * DIM + lane * 4;
    // vector reduction: 1 L2 atomic op per 16B instead of 4 scalar REDGs
    asm volatile("red.global.add.v4.f32 [%0], {%1,%2,%3,%4};"
                 :: "l"(p), "f"(mx), "f"(my), "f"(mz), "f"(mw) : "memory");
}

// ---------------- DistMult decoder ----------------
__global__ void __launch_bounds__(256) k_decode(const int* __restrict__ src,
                                                const int* __restrict__ dst,
                                                const int* __restrict__ et,
                                                const float* __restrict__ rel,
                                                float* __restrict__ out)
{
    int e = (blockIdx.x * blockDim.x + threadIdx.x) >> 5;
    int lane = threadIdx.x & 31;
    if (e >= NEDGE) return;
    int s = src[e];
    int d = dst[e];
    int t = et[e];
    float4 a = *(const float4*)&g_h2[(long long)s * DIM + lane * 4];
    float4 b = *(const float4*)&g_h2[(long long)d * DIM + lane * 4];
    float4 r = *(const float4*)&rel[t * DIM + lane * 4];
    float dot = a.x * r.x * b.x + a.y * r.y * b.y + a.z * r.z * b.z + a.w * r.w * b.w;
#pragma unroll
    for (int o = 16; o > 0; o >>= 1) dot += __shfl_xor_sync(0xffffffffu, dot, o);
    if (lane == 0) out[e] = dot;
}

// ---------------- L2 penalty on rel_emb ----------------
__global__ void k_penalty(const float* __restrict__ rel, float* __restrict__ out, int idx)
{
    __shared__ float red[8];
    float s = 0.f;
    for (int i = threadIdx.x; i < R2 * DIM; i += 256) {
        float v = rel[i];
        s += v * v;
    }
#pragma unroll
    for (int o = 16; o > 0; o >>= 1) s += __shfl_xor_sync(0xffffffffu, s, o);
    if ((threadIdx.x & 31) == 0) red[threadIdx.x >> 5] = s;
    __syncthreads();
    if (threadIdx.x < 8) {
        s = red[threadIdx.x];
#pragma unroll
        for (int o = 4; o > 0; o >>= 1) s += __shfl_xor_sync(0x000000ffu, s, o);
        if (threadIdx.x == 0) out[idx] = s;
    }
}

extern "C" void kernel_launch(void* const* d_in, const int* in_sizes, int n_in,
                              void* d_out, int out_size)
{
    const int* edge_index = (const int*)d_in[0];
    const int* src = edge_index;             // edge_index[0, :]
    const int* dst = edge_index + NEDGE;     // edge_index[1, :]
    const int* et  = (const int*)d_in[1];
    const float* emb    = (const float*)d_in[2];
    const float* ebias  = (const float*)d_in[3];
    const float* bases1 = (const float*)d_in[4];
    const float* comp1  = (const float*)d_in[5];
    const float* root1  = (const float*)d_in[6];
    const float* bias1  = (const float*)d_in[7];
    const float* bases2 = (const float*)d_in[8];
    const float* comp2  = (const float*)d_in[9];
    const float* root2  = (const float*)d_in[10];
    const float* bias2  = (const float*)d_in[11];
    const float* rel    = (const float*)d_in[12];
    float* out = (float*)d_out;

    // schlichtkrull norm: counts over (dst, relation)
    k_zero_counts<<<(N_ENT * R2 + 255) / 256, 256>>>();
    k_hist<<<(NEDGE + 255) / 256, 256>>>(dst, et);

    dim3 gg((N_ENT + 127) / 128, WCOLS / 64);

    // layer 1: x0 = relu(emb + ebias) fused into GEMM input
    k_build_w<<<(DIM * WCOLS) / 256, 256>>>(bases1, root1);
    k_gemm<0><<<gg, 256>>>(emb, ebias, bias1);
    k_edge<0><<<NEDGE / 8, 256>>>(src, dst, et, comp1);

    // layer 2: x1 = relu(h1) fused into GEMM input
    k_build_w<<<(DIM * WCOLS) / 256, 256>>>(bases2, root2);
    k_gemm<1><<<gg, 256>>>(nullptr, nullptr, bias2);
    k_edge<1><<<NEDGE / 8, 256>>>(src, dst, et, comp2);

    // decoder + penalty
    k_decode<<<NEDGE / 8, 256>>>(src, dst, et, rel, out);
    if (out_size > NEDGE)
        k_penalty<<<1, 256>>>(rel, out, out_size - 1);
}

// round 5
// speedup vs baseline: 1.7006x; 1.7006x over previous
#include <cuda_runtime.h>
#include <cuda_bf16.h>
#include <cstdint>

#define N_ENT  100000
#define DIM    128
#define R2     100
#define NBASES 4
#define NEDGE  400000
#define WCOLS  640

// ---- scratch (device globals; no allocation allowed) ----
__device__ __align__(16) int   g_counts[N_ENT * R2];              // 40 MB
__device__ __align__(16) float g_xb[(long long)N_ENT * 512];      // 204.8 MB
__device__ __align__(16) float g_h1[N_ENT * DIM];                 // 51.2 MB
__device__ __align__(16) float g_h2[N_ENT * DIM];                 // 51.2 MB
// pre-swizzled W^T tiles: 5 tiles of [128 rows(N) x 128 cols(K)] bf16, hi/lo split
__device__ __align__(1024) unsigned char g_wt_hi[5 * 32768];
__device__ __align__(1024) unsigned char g_wt_lo[5 * 32768];

// blocked K-major SW128 layout for a 128x128 bf16 tile:
// atom = 8 rows x 64 cols (1024B); off = ((r>>3)<<10)+((c>>6)<<14)+((r&7)<<7)+((c&63)<<1), XOR swizzle
__device__ __host__ __forceinline__ uint32_t tile_off(int row, int col) {
    uint32_t b = ((uint32_t)(row >> 3) << 10) + ((uint32_t)(col >> 6) << 14)
               + ((uint32_t)(row & 7) << 7) + ((uint32_t)(col & 63) << 1);
    return b ^ ((b >> 3) & 0x70);
}

__device__ __forceinline__ uint32_t smem_u32(const void* p) {
    uint32_t a;
    asm("{ .reg .u64 t; cvta.to.shared.u64 t, %1; cvt.u32.u64 %0, t; }" : "=r"(a) : "l"(p));
    return a;
}

__device__ __forceinline__ void ldsm4(uint32_t* r, uint32_t addr) {
    asm volatile("ldmatrix.sync.aligned.m8n8.x4.shared.b16 {%0,%1,%2,%3}, [%4];"
                 : "=r"(r[0]), "=r"(r[1]), "=r"(r[2]), "=r"(r[3]) : "r"(addr));
}

__device__ __forceinline__ void mma16816(float* d, const uint32_t* a, const uint32_t* b) {
    asm volatile("mma.sync.aligned.m16n8k16.row.col.f32.bf16.bf16.f32 "
                 "{%0,%1,%2,%3}, {%4,%5,%6,%7}, {%8,%9}, {%0,%1,%2,%3};"
                 : "+f"(d[0]), "+f"(d[1]), "+f"(d[2]), "+f"(d[3])
                 : "r"(a[0]), "r"(a[1]), "r"(a[2]), "r"(a[3]), "r"(b[0]), "r"(b[1]));
}

// ---------------- norm precompute ----------------
__global__ void k_zero_counts() {
    int i = blockIdx.x * blockDim.x + threadIdx.x;
    if (i < N_ENT * R2) g_counts[i] = 0;
}
__global__ void k_hist(const int* __restrict__ dst, const int* __restrict__ et) {
    int e = blockIdx.x * blockDim.x + threadIdx.x;
    if (e < NEDGE) atomicAdd(&g_counts[dst[e] * R2 + et[e]], 1);
}

// ---------------- build pre-swizzled W^T hi/lo tiles ----------------
__global__ void k_build_wt(const float* __restrict__ bases, const float* __restrict__ root) {
    int idx = blockIdx.x * blockDim.x + threadIdx.x;   // 640*128
    if (idx >= WCOLS * DIM) return;
    int c = idx >> 7;     // output column 0..639 (= W^T row n)
    int k = idx & 127;    // K index
    float v;
    if (c < 512) {
        int b = c >> 7, h = c & 127;
        v = bases[(b * DIM + k) * DIM + h];   // bases[b, k, h]
    } else {
        v = root[k * DIM + (c - 512)];
    }
    __nv_bfloat16 hh = __float2bfloat16(v);
    __nv_bfloat16 ll = __float2bfloat16(v - __bfloat162float(hh));
    int nt = (c < 512) ? (c >> 7) : 4;
    int rt = c & 127;
    uint32_t off = tile_off(rt, k);
    *(unsigned short*)(g_wt_hi + nt * 32768 + off) = __bfloat16_as_ushort(hh);
    *(unsigned short*)(g_wt_lo + nt * 32768 + off) = __bfloat16_as_ushort(ll);
}

// ---------------- HMMA GEMM:  act(X)[128x128-rows] @ W[128x640] ----------------
// MODE 0: act = relu(x + inb), X = Xp, agg = g_h1
// MODE 1: act = relu(x),       X = g_h1, agg = g_h2
// split-bf16: D = Ah*Wh + Ah*Wl + Al*Wh, fp32 accumulate in registers.
// smem: A_hi[32K] A_lo[32K] W_hi[32K] W_lo[32K] = 128KB. One CTA stages all of K=128.
// grid = (5 W-tiles, 782 row-blocks): W-tile index fastest -> W stays L2-hot.
template<int MODE>
__global__ void __launch_bounds__(256, 1) k_gemm_mma(const float* __restrict__ Xp,
                                                     const float* __restrict__ inb,
                                                     const float* __restrict__ outb)
{
    extern __shared__ unsigned char smem[];
    const uint32_t sb = smem_u32(smem);
    const float* __restrict__ X = (MODE == 0) ? Xp : (const float*)g_h1;

    const int tid  = threadIdx.x;
    const int lane = tid & 31;
    const int wid  = tid >> 5;
    const int nt   = blockIdx.x;          // 0..4 (which W tile / output 128-col group)
    const int row0 = blockIdx.y * 128;

    // ---- stage A tile: fp32 -> (+bias) -> relu -> bf16 hi/lo, swizzled ----
    {
        const int row = tid >> 1;
        const int colbase = (tid & 1) * 64;
        const int gr = row0 + row;
        const bool ok = gr < N_ENT;
        const uint32_t C = ((uint32_t)(row >> 3) << 10) + ((uint32_t)(row & 7) << 7);
        const uint32_t swz = (uint32_t)(row & 7) << 4;
#pragma unroll
        for (int j = 0; j < 16; j++) {
            const int col = colbase + j * 4;
            float4 v = ok ? *(const float4*)(X + (size_t)gr * DIM + col)
                          : make_float4(0.f, 0.f, 0.f, 0.f);
            if (MODE == 0 && ok) {
                float4 b = *(const float4*)(inb + col);
                v.x += b.x; v.y += b.y; v.z += b.z; v.w += b.w;
            }
            v.x = fmaxf(v.x, 0.f); v.y = fmaxf(v.y, 0.f);
            v.z = fmaxf(v.z, 0.f); v.w = fmaxf(v.w, 0.f);
            __nv_bfloat16 h0 = __float2bfloat16(v.x), h1 = __float2bfloat16(v.y);
            __nv_bfloat16 h2 = __float2bfloat16(v.z), h3 = __float2bfloat16(v.w);
            __nv_bfloat16 l0 = __float2bfloat16(v.x - __bfloat162float(h0));
            __nv_bfloat16 l1 = __float2bfloat16(v.y - __bfloat162float(h1));
            __nv_bfloat16 l2 = __float2bfloat16(v.z - __bfloat162float(h2));
            __nv_bfloat16 l3 = __float2bfloat16(v.w - __bfloat162float(h3));
            uint2 hp, lp;
            hp.x = (uint32_t)__bfloat16_as_ushort(h0) | ((uint32_t)__bfloat16_as_ushort(h1) << 16);
            hp.y = (uint32_t)__bfloat16_as_ushort(h2) | ((uint32_t)__bfloat16_as_ushort(h3) << 16);
            lp.x = (uint32_t)__bfloat16_as_ushort(l0) | ((uint32_t)__bfloat16_as_ushort(l1) << 16);
            lp.y = (uint32_t)__bfloat16_as_ushort(l2) | ((uint32_t)__bfloat16_as_ushort(l3) << 16);
            const uint32_t cp = ((uint32_t)(col >> 6) << 14) + ((uint32_t)(col & 63) << 1);
            const uint32_t off = (C + cp) ^ swz;
            *(uint2*)(smem + off)         = hp;
            *(uint2*)(smem + 32768 + off) = lp;
        }
    }
    // ---- stage W tile (pre-swizzled, straight copy) ----
    {
        const uint4* sh = (const uint4*)(g_wt_hi + nt * 32768);
        const uint4* sl = (const uint4*)(g_wt_lo + nt * 32768);
        uint4* dh = (uint4*)(smem + 65536);
        uint4* dl = (uint4*)(smem + 98304);
#pragma unroll
        for (int i = 0; i < 8; i++) {
            dh[tid + i * 256] = sh[tid + i * 256];
            dl[tid + i * 256] = sl[tid + i * 256];
        }
    }
    __syncthreads();

    // ---- compute: warp tile 64(m) x 32(n); 8 warps = 2(m) x 4(n) ----
    const int wm = wid & 1;
    const int wn = wid >> 1;

    float acc[4][4][4];
#pragma unroll
    for (int mi = 0; mi < 4; mi++)
#pragma unroll
        for (int ni = 0; ni < 4; ni++)
#pragma unroll
            for (int q = 0; q < 4; q++) acc[mi][ni][q] = 0.f;

    const uint32_t swz = (uint32_t)(lane & 7) << 4;
    const uint32_t koffA = (uint32_t)(lane & 16) >> 1;   // +8 cols for upper half
    const uint32_t koffB = (uint32_t)(lane & 8);
    uint32_t preA[4], preB[2];
#pragma unroll
    for (int mi = 0; mi < 4; mi++) {
        int r = wm * 64 + mi * 16 + (lane & 15);
        preA[mi] = sb + (((uint32_t)(r >> 3) << 10) + ((uint32_t)(r & 7) << 7));
    }
#pragma unroll
    for (int nj = 0; nj < 2; nj++) {
        int r = wn * 32 + nj * 16 + ((lane & 16) >> 1) + (lane & 7);
        preB[nj] = sb + 65536 + (((uint32_t)(r >> 3) << 10) + ((uint32_t)(r & 7) << 7));
    }

#pragma unroll
    for (int kk = 0; kk < 8; kk++) {
        const int k = kk * 16;
        const uint32_t colA = k + koffA;
        const uint32_t colB = k + koffB;
        const uint32_t cpA = ((colA & 64) << 8) + ((colA & 63) << 1);
        const uint32_t cpB = ((colB & 64) << 8) + ((colB & 63) << 1);

        uint32_t ah[4][4], wh[4][2], wl[4][2];
#pragma unroll
        for (int mi = 0; mi < 4; mi++)
            ldsm4(ah[mi], (preA[mi] + cpA) ^ swz);
#pragma unroll
        for (int nj = 0; nj < 2; nj++) {
            uint32_t t[4];
            ldsm4(t, (preB[nj] + cpB) ^ swz);
            wh[2 * nj][0] = t[0]; wh[2 * nj][1] = t[1];
            wh[2 * nj + 1][0] = t[2]; wh[2 * nj + 1][1] = t[3];
        }
#pragma unroll
        for (int nj = 0; nj < 2; nj++) {
            uint32_t t[4];
            ldsm4(t, (preB[nj] + 32768 + cpB) ^ swz);
            wl[2 * nj][0] = t[0]; wl[2 * nj][1] = t[1];
            wl[2 * nj + 1][0] = t[2]; wl[2 * nj + 1][1] = t[3];
        }
        // Ah * Wh
#pragma unroll
        for (int mi = 0; mi < 4; mi++)
#pragma unroll
            for (int ni = 0; ni < 4; ni++)
                mma16816(acc[mi][ni], ah[mi], wh[ni]);
        // Ah * Wl
#pragma unroll
        for (int mi = 0; mi < 4; mi++)
#pragma unroll
            for (int ni = 0; ni < 4; ni++)
                mma16816(acc[mi][ni], ah[mi], wl[ni]);
        // Al * Wh (reuse ah regs)
#pragma unroll
        for (int mi = 0; mi < 4; mi++)
            ldsm4(ah[mi], (preA[mi] + 32768 + cpA) ^ swz);
#pragma unroll
        for (int mi = 0; mi < 4; mi++)
#pragma unroll
            for (int ni = 0; ni < 4; ni++)
                mma16816(acc[mi][ni], ah[mi], wh[ni]);
    }

    // ---- epilogue ----
    float* agg = (MODE == 0) ? g_h1 : g_h2;
#pragma unroll
    for (int mi = 0; mi < 4; mi++) {
        const int gr0 = row0 + wm * 64 + mi * 16 + (lane >> 2);
#pragma unroll
        for (int half = 0; half < 2; half++) {
            const int gr = gr0 + half * 8;
            if (gr >= N_ENT) continue;
#pragma unroll
            for (int ni = 0; ni < 4; ni++) {
                const int n = wn * 32 + ni * 8 + (lane & 3) * 2;
                float2 o;
                o.x = acc[mi][ni][half * 2 + 0];
                o.y = acc[mi][ni][half * 2 + 1];
                if (nt < 4) {
                    *(float2*)(g_xb + (size_t)gr * 512 + nt * 128 + n) = o;
                } else {
                    float2 b = *(const float2*)(outb + n);
                    o.x += b.x; o.y += b.y;
                    *(float2*)(agg + (size_t)gr * DIM + n) = o;
                }
            }
        }
    }
}

// ---------------- edge pass: mix basis projections, scatter-add ----------------
template<int LAYER>
__global__ void __launch_bounds__(256) k_edge(const int* __restrict__ src,
                                              const int* __restrict__ dst,
                                              const int* __restrict__ et,
                                              const float* __restrict__ comp)
{
    int e = (blockIdx.x * blockDim.x + threadIdx.x) >> 5;
    int lane = threadIdx.x & 31;
    if (e >= NEDGE) return;
    int s = src[e], d = dst[e], t = et[e];
    float norm = 1.0f / fmaxf((float)g_counts[d * R2 + t], 1.0f);
    float c0 = comp[t * 4 + 0] * norm;
    float c1 = comp[t * 4 + 1] * norm;
    float c2 = comp[t * 4 + 2] * norm;
    float c3 = comp[t * 4 + 3] * norm;
    const float4* xb = (const float4*)(g_xb + (long long)s * 512);
    float4 v0 = xb[lane], v1 = xb[32 + lane], v2 = xb[64 + lane], v3 = xb[96 + lane];
    float mx = c0 * v0.x + c1 * v1.x + c2 * v2.x + c3 * v3.x;
    float my = c0 * v0.y + c1 * v1.y + c2 * v2.y + c3 * v3.y;
    float mz = c0 * v0.z + c1 * v1.z + c2 * v2.z + c3 * v3.z;
    float mw = c0 * v0.w + c1 * v1.w + c2 * v2.w + c3 * v3.w;
    float* agg = (LAYER == 0) ? g_h1 : g_h2;
    float* p = agg + d * DIM + lane * 4;
    asm volatile("red.global.add.v4.f32 [%0], {%1,%2,%3,%4};"
                 :: "l"(p), "f"(mx), "f"(my), "f"(mz), "f"(mw) : "memory");
}

// ---------------- DistMult decoder ----------------
__global__ void __launch_bounds__(256) k_decode(const int* __restrict__ src,
                                                const int* __restrict__ dst,
                                                const int* __restrict__ et,
                                                const float* __restrict__ rel,
                                                float* __restrict__ out)
{
    int e = (blockIdx.x * blockDim.x + threadIdx.x) >> 5;
    int lane = threadIdx.x & 31;
    if (e >= NEDGE) return;
    int s = src[e], d = dst[e], t = et[e];
    float4 a = *(const float4*)&g_h2[(long long)s * DIM + lane * 4];
    float4 b = *(const float4*)&g_h2[(long long)d * DIM + lane * 4];
    float4 r = *(const float4*)&rel[t * DIM + lane * 4];
    float dot = a.x * r.x * b.x + a.y * r.y * b.y + a.z * r.z * b.z + a.w * r.w * b.w;
#pragma unroll
    for (int o = 16; o > 0; o >>= 1) dot += __shfl_xor_sync(0xffffffffu, dot, o);
    if (lane == 0) out[e] = dot;
}

__global__ void k_penalty(const float* __restrict__ rel, float* __restrict__ out, int idx)
{
    __shared__ float red[8];
    float s = 0.f;
    for (int i = threadIdx.x; i < R2 * DIM; i += 256) { float v = rel[i]; s += v * v; }
#pragma unroll
    for (int o = 16; o > 0; o >>= 1) s += __shfl_xor_sync(0xffffffffu, s, o);
    if ((threadIdx.x & 31) == 0) red[threadIdx.x >> 5] = s;
    __syncthreads();
    if (threadIdx.x < 8) {
        s = red[threadIdx.x];
#pragma unroll
        for (int o = 4; o > 0; o >>= 1) s += __shfl_xor_sync(0x000000ffu, s, o);
        if (threadIdx.x == 0) out[idx] = s;
    }
}

extern "C" void kernel_launch(void* const* d_in, const int* in_sizes, int n_in,
                              void* d_out, int out_size)
{
    const int* edge_index = (const int*)d_in[0];
    const int* src = edge_index;
    const int* dst = edge_index + NEDGE;
    const int* et  = (const int*)d_in[1];
    const float* emb    = (const float*)d_in[2];
    const float* ebias  = (const float*)d_in[3];
    const float* bases1 = (const float*)d_in[4];
    const float* comp1  = (const float*)d_in[5];
    const float* root1  = (const float*)d_in[6];
    const float* bias1  = (const float*)d_in[7];
    const float* bases2 = (const float*)d_in[8];
    const float* comp2  = (const float*)d_in[9];
    const float* root2  = (const float*)d_in[10];
    const float* bias2  = (const float*)d_in[11];
    const float* rel    = (const float*)d_in[12];
    float* out = (float*)d_out;

    static bool attr_done = false;
    if (!attr_done) {
        cudaFuncSetAttribute(k_gemm_mma<0>, cudaFuncAttributeMaxDynamicSharedMemorySize, 131072);
        cudaFuncSetAttribute(k_gemm_mma<1>, cudaFuncAttributeMaxDynamicSharedMemorySize, 131072);
        attr_done = true;
    }

    k_zero_counts<<<(N_ENT * R2 + 255) / 256, 256>>>();
    k_hist<<<(NEDGE + 255) / 256, 256>>>(dst, et);

    const dim3 gg(5, (N_ENT + 127) / 128);   // (W tiles, row blocks)

    k_build_wt<<<(WCOLS * DIM + 255) / 256, 256>>>(bases1, root1);
    k_gemm_mma<0><<<gg, 256, 131072>>>(emb, ebias, bias1);
    k_edge<0><<<NEDGE / 8, 256>>>(src, dst, et, comp1);

    k_build_wt<<<(WCOLS * DIM + 255) / 256, 256>>>(bases2, root2);
    k_gemm_mma<1><<<gg, 256, 131072>>>(emb, nullptr, bias2);
    k_edge<1><<<NEDGE / 8, 256>>>(src, dst, et, comp2);

    k_decode<<<NEDGE / 8, 256>>>(src, dst, et, rel, out);
    if (out_size > NEDGE)
        k_penalty<<<1, 256>>>(rel, out, out_size - 1);
}

// round 6
// speedup vs baseline: 2.3379x; 1.3747x over previous
#include <cuda_runtime.h>
#include <cuda_bf16.h>
#include <cuda_fp16.h>
#include <cstdint>

#define N_ENT  100000
#define DIM    128
#define R2     100
#define NBASES 4
#define NEDGE  400000
#define WCOLS  640

// ---- scratch (device globals; no allocation allowed) ----
__device__ __align__(16) int    g_counts[N_ENT * R2];               // 40 MB
__device__ __align__(16) __half g_xb_h[(size_t)N_ENT * 512];        // 102.4 MB
__device__ __align__(16) float  g_h1[N_ENT * DIM];                  // 51.2 MB
__device__ __align__(16) float  g_h2[N_ENT * DIM];                  // 51.2 MB
// pre-swizzled W^T tiles: 5 tiles of [128 rows(N) x 128 cols(K)] bf16, hi/lo split
__device__ __align__(1024) unsigned char g_wt_hi[5 * 32768];
__device__ __align__(1024) unsigned char g_wt_lo[5 * 32768];

// blocked K-major SW128 layout for a 128x128 bf16 tile
__device__ __host__ __forceinline__ uint32_t tile_off(int row, int col) {
    uint32_t b = ((uint32_t)(row >> 3) << 10) + ((uint32_t)(col >> 6) << 14)
               + ((uint32_t)(row & 7) << 7) + ((uint32_t)(col & 63) << 1);
    return b ^ ((b >> 3) & 0x70);
}

__device__ __forceinline__ uint32_t smem_u32(const void* p) {
    uint32_t a;
    asm("{ .reg .u64 t; cvta.to.shared.u64 t, %1; cvt.u32.u64 %0, t; }" : "=r"(a) : "l"(p));
    return a;
}

__device__ __forceinline__ void ldsm4(uint32_t* r, uint32_t addr) {
    asm volatile("ldmatrix.sync.aligned.m8n8.x4.shared.b16 {%0,%1,%2,%3}, [%4];"
                 : "=r"(r[0]), "=r"(r[1]), "=r"(r[2]), "=r"(r[3]) : "r"(addr));
}

__device__ __forceinline__ void mma16816(float* d, const uint32_t* a, const uint32_t* b) {
    asm volatile("mma.sync.aligned.m16n8k16.row.col.f32.bf16.bf16.f32 "
                 "{%0,%1,%2,%3}, {%4,%5,%6,%7}, {%8,%9}, {%0,%1,%2,%3};"
                 : "+f"(d[0]), "+f"(d[1]), "+f"(d[2]), "+f"(d[3])
                 : "r"(a[0]), "r"(a[1]), "r"(a[2]), "r"(a[3]), "r"(b[0]), "r"(b[1]));
}

// async-copy one W tile (hi+lo, 64KB) into smem buffer `buf`
__device__ __forceinline__ void cp_w_tile(uint32_t sb, int nt, int buf, int tid) {
    const uint4* sh = (const uint4*)(g_wt_hi + nt * 32768) + tid;
    const uint4* sl = (const uint4*)(g_wt_lo + nt * 32768) + tid;
    uint32_t dh = sb + 65536 + (uint32_t)buf * 65536 + (uint32_t)tid * 16;
    uint32_t dl = dh + 32768;
#pragma unroll
    for (int i = 0; i < 8; i++) {
        asm volatile("cp.async.cg.shared.global [%0], [%1], 16;"
                     :: "r"(dh + i * 4096), "l"(sh + i * 256));
        asm volatile("cp.async.cg.shared.global [%0], [%1], 16;"
                     :: "r"(dl + i * 4096), "l"(sl + i * 256));
    }
    asm volatile("cp.async.commit_group;");
}

// ---------------- norm precompute ----------------
__global__ void k_zero_counts() {
    int i = blockIdx.x * blockDim.x + threadIdx.x;
    if (i < N_ENT * R2) g_counts[i] = 0;
}
__global__ void k_hist(const int* __restrict__ dst, const int* __restrict__ et) {
    int e = blockIdx.x * blockDim.x + threadIdx.x;
    if (e < NEDGE) atomicAdd(&g_counts[dst[e] * R2 + et[e]], 1);
}

// ---------------- build pre-swizzled W^T hi/lo tiles ----------------
__global__ void k_build_wt(const float* __restrict__ bases, const float* __restrict__ root) {
    int idx = blockIdx.x * blockDim.x + threadIdx.x;   // 640*128
    if (idx >= WCOLS * DIM) return;
    int c = idx >> 7;     // output column 0..639 (= W^T row n)
    int k = idx & 127;    // K index
    float v;
    if (c < 512) {
        int b = c >> 7, h = c & 127;
        v = bases[(b * DIM + k) * DIM + h];   // bases[b, k, h]
    } else {
        v = root[k * DIM + (c - 512)];
    }
    __nv_bfloat16 hh = __float2bfloat16(v);
    __nv_bfloat16 ll = __float2bfloat16(v - __bfloat162float(hh));
    int nt = (c < 512) ? (c >> 7) : 4;
    int rt = c & 127;
    uint32_t off = tile_off(rt, k);
    *(unsigned short*)(g_wt_hi + nt * 32768 + off) = __bfloat16_as_ushort(hh);
    *(unsigned short*)(g_wt_lo + nt * 32768 + off) = __bfloat16_as_ushort(ll);
}

// ---------------- HMMA GEMM: act(X)[128 rows x 128] @ W[128x640] ----------------
// grid = 782 row-blocks; per CTA: stage A once, loop over 5 W tiles with
// cp.async double buffering. split-bf16: D = Ah*Wh + Ah*Wl + Al*Wh.
// smem: A_hi[32K] A_lo[32K] | W buf0 hi/lo [64K] | W buf1 hi/lo [64K] = 192KB
template<int MODE>
__global__ void __launch_bounds__(256, 1) k_gemm_mma(const float* __restrict__ Xp,
                                                     const float* __restrict__ inb,
                                                     const float* __restrict__ outb)
{
    extern __shared__ unsigned char smem[];
    const uint32_t sb = smem_u32(smem);
    const float* __restrict__ X = (MODE == 0) ? Xp : (const float*)g_h1;

    const int tid  = threadIdx.x;
    const int lane = tid & 31;
    const int wid  = tid >> 5;
    const int row0 = blockIdx.x * 128;

    // kick off W tile 0 prefetch first
    cp_w_tile(sb, 0, 0, tid);

    // ---- stage A tile: fp32 -> (+bias) -> relu -> bf16 hi/lo, swizzled ----
    {
        const int row = tid >> 1;
        const int colbase = (tid & 1) * 64;
        const int gr = row0 + row;
        const bool ok = gr < N_ENT;
        const uint32_t C = ((uint32_t)(row >> 3) << 10) + ((uint32_t)(row & 7) << 7);
        const uint32_t swz = (uint32_t)(row & 7) << 4;
#pragma unroll
        for (int j = 0; j < 16; j++) {
            const int col = colbase + j * 4;
            float4 v = ok ? *(const float4*)(X + (size_t)gr * DIM + col)
                          : make_float4(0.f, 0.f, 0.f, 0.f);
            if (MODE == 0 && ok) {
                float4 b = *(const float4*)(inb + col);
                v.x += b.x; v.y += b.y; v.z += b.z; v.w += b.w;
            }
            v.x = fmaxf(v.x, 0.f); v.y = fmaxf(v.y, 0.f);
            v.z = fmaxf(v.z, 0.f); v.w = fmaxf(v.w, 0.f);
            __nv_bfloat16 h0 = __float2bfloat16(v.x), h1 = __float2bfloat16(v.y);
            __nv_bfloat16 h2 = __float2bfloat16(v.z), h3 = __float2bfloat16(v.w);
            __nv_bfloat16 l0 = __float2bfloat16(v.x - __bfloat162float(h0));
            __nv_bfloat16 l1 = __float2bfloat16(v.y - __bfloat162float(h1));
            __nv_bfloat16 l2 = __float2bfloat16(v.z - __bfloat162float(h2));
            __nv_bfloat16 l3 = __float2bfloat16(v.w - __bfloat162float(h3));
            uint2 hp, lp;
            hp.x = (uint32_t)__bfloat16_as_ushort(h0) | ((uint32_t)__bfloat16_as_ushort(h1) << 16);
            hp.y = (uint32_t)__bfloat16_as_ushort(h2) | ((uint32_t)__bfloat16_as_ushort(h3) << 16);
            lp.x = (uint32_t)__bfloat16_as_ushort(l0) | ((uint32_t)__bfloat16_as_ushort(l1) << 16);
            lp.y = (uint32_t)__bfloat16_as_ushort(l2) | ((uint32_t)__bfloat16_as_ushort(l3) << 16);
            const uint32_t cp = ((uint32_t)(col >> 6) << 14) + ((uint32_t)(col & 63) << 1);
            const uint32_t off = (C + cp) ^ swz;
            *(uint2*)(smem + off)         = hp;
            *(uint2*)(smem + 32768 + off) = lp;
        }
    }

    // ---- per-warp fragment address precompute ----
    const int wm = wid & 1;
    const int wn = wid >> 1;
    const uint32_t swz = (uint32_t)(lane & 7) << 4;
    const uint32_t koffA = (uint32_t)(lane & 16) >> 1;
    const uint32_t koffB = (uint32_t)(lane & 8);
    uint32_t preA[4], preBoff[2];
#pragma unroll
    for (int mi = 0; mi < 4; mi++) {
        int r = wm * 64 + mi * 16 + (lane & 15);
        preA[mi] = sb + (((uint32_t)(r >> 3) << 10) + ((uint32_t)(r & 7) << 7));
    }
#pragma unroll
    for (int nj = 0; nj < 2; nj++) {
        int r = wn * 32 + nj * 16 + ((lane & 16) >> 1) + (lane & 7);
        preBoff[nj] = ((uint32_t)(r >> 3) << 10) + ((uint32_t)(r & 7) << 7);
    }

    float* agg = (MODE == 0) ? g_h1 : g_h2;

    for (int nt = 0; nt < 5; nt++) {
        if (nt < 4) {
            cp_w_tile(sb, nt + 1, (nt + 1) & 1, tid);
            asm volatile("cp.async.wait_group 1;" ::: "memory");
        } else {
            asm volatile("cp.async.wait_group 0;" ::: "memory");
        }
        __syncthreads();   // W tile nt ready; (iter 0: also publishes A stores)

        const uint32_t wbase = sb + 65536 + (uint32_t)(nt & 1) * 65536;
        uint32_t preB[2] = { wbase + preBoff[0], wbase + preBoff[1] };

        float acc[4][4][4];
#pragma unroll
        for (int mi = 0; mi < 4; mi++)
#pragma unroll
            for (int ni = 0; ni < 4; ni++)
#pragma unroll
                for (int q = 0; q < 4; q++) acc[mi][ni][q] = 0.f;

#pragma unroll
        for (int kk = 0; kk < 8; kk++) {
            const int k = kk * 16;
            const uint32_t colA = k + koffA;
            const uint32_t colB = k + koffB;
            const uint32_t cpA = ((colA & 64) << 8) + ((colA & 63) << 1);
            const uint32_t cpB = ((colB & 64) << 8) + ((colB & 63) << 1);

            uint32_t ah[4][4], wh[4][2], wl[4][2];
#pragma unroll
            for (int mi = 0; mi < 4; mi++)
                ldsm4(ah[mi], (preA[mi] + cpA) ^ swz);
#pragma unroll
            for (int nj = 0; nj < 2; nj++) {
                uint32_t t[4];
                ldsm4(t, (preB[nj] + cpB) ^ swz);
                wh[2 * nj][0] = t[0]; wh[2 * nj][1] = t[1];
                wh[2 * nj + 1][0] = t[2]; wh[2 * nj + 1][1] = t[3];
            }
#pragma unroll
            for (int nj = 0; nj < 2; nj++) {
                uint32_t t[4];
                ldsm4(t, (preB[nj] + 32768 + cpB) ^ swz);
                wl[2 * nj][0] = t[0]; wl[2 * nj][1] = t[1];
                wl[2 * nj + 1][0] = t[2]; wl[2 * nj + 1][1] = t[3];
            }
            // Ah*Wh
#pragma unroll
            for (int mi = 0; mi < 4; mi++)
#pragma unroll
                for (int ni = 0; ni < 4; ni++)
                    mma16816(acc[mi][ni], ah[mi], wh[ni]);
            // Ah*Wl
#pragma unroll
            for (int mi = 0; mi < 4; mi++)
#pragma unroll
                for (int ni = 0; ni < 4; ni++)
                    mma16816(acc[mi][ni], ah[mi], wl[ni]);
            // Al*Wh
#pragma unroll
            for (int mi = 0; mi < 4; mi++)
                ldsm4(ah[mi], (preA[mi] + 32768 + cpA) ^ swz);
#pragma unroll
            for (int mi = 0; mi < 4; mi++)
#pragma unroll
                for (int ni = 0; ni < 4; ni++)
                    mma16816(acc[mi][ni], ah[mi], wh[ni]);
        }

        // ---- epilogue for this nt ----
#pragma unroll
        for (int mi = 0; mi < 4; mi++) {
            const int gr0 = row0 + wm * 64 + mi * 16 + (lane >> 2);
#pragma unroll
            for (int half = 0; half < 2; half++) {
                const int gr = gr0 + half * 8;
                if (gr >= N_ENT) continue;
#pragma unroll
                for (int ni = 0; ni < 4; ni++) {
                    const int n = wn * 32 + ni * 8 + (lane & 3) * 2;
                    float2 o;
                    o.x = acc[mi][ni][half * 2 + 0];
                    o.y = acc[mi][ni][half * 2 + 1];
                    if (nt < 4) {
                        *(__half2*)(g_xb_h + (size_t)gr * 512 + nt * 128 + n) =
                            __float22half2_rn(o);
                    } else {
                        float2 b = *(const float2*)(outb + n);
                        o.x += b.x; o.y += b.y;
                        *(float2*)(agg + (size_t)gr * DIM + n) = o;
                    }
                }
            }
        }
        __syncthreads();   // all warps done with buffer before it is overwritten
    }
}

// ---------------- edge pass: mix basis projections (fp16 xb), scatter-add ----------------
__device__ __forceinline__ float4 ld_xb4(const __half* p) {
    uint2 u = *(const uint2*)p;
    __half2 a = *reinterpret_cast<__half2*>(&u.x);
    __half2 b = *reinterpret_cast<__half2*>(&u.y);
    float2 fa = __half22float2(a), fb = __half22float2(b);
    return make_float4(fa.x, fa.y, fb.x, fb.y);
}

template<int LAYER>
__global__ void __launch_bounds__(256) k_edge(const int* __restrict__ src,
                                              const int* __restrict__ dst,
                                              const int* __restrict__ et,
                                              const float* __restrict__ comp)
{
    int e = (blockIdx.x * blockDim.x + threadIdx.x) >> 5;
    int lane = threadIdx.x & 31;
    if (e >= NEDGE) return;
    int s = src[e], d = dst[e], t = et[e];
    float norm = 1.0f / fmaxf((float)g_counts[d * R2 + t], 1.0f);
    float c0 = comp[t * 4 + 0] * norm;
    float c1 = comp[t * 4 + 1] * norm;
    float c2 = comp[t * 4 + 2] * norm;
    float c3 = comp[t * 4 + 3] * norm;
    const __half* xb = g_xb_h + (size_t)s * 512 + lane * 4;
    float4 v0 = ld_xb4(xb);
    float4 v1 = ld_xb4(xb + 128);
    float4 v2 = ld_xb4(xb + 256);
    float4 v3 = ld_xb4(xb + 384);
    float mx = c0 * v0.x + c1 * v1.x + c2 * v2.x + c3 * v3.x;
    float my = c0 * v0.y + c1 * v1.y + c2 * v2.y + c3 * v3.y;
    float mz = c0 * v0.z + c1 * v1.z + c2 * v2.z + c3 * v3.z;
    float mw = c0 * v0.w + c1 * v1.w + c2 * v2.w + c3 * v3.w;
    float* agg = (LAYER == 0) ? g_h1 : g_h2;
    float* p = agg + d * DIM + lane * 4;
    asm volatile("red.global.add.v4.f32 [%0], {%1,%2,%3,%4};"
                 :: "l"(p), "f"(mx), "f"(my), "f"(mz), "f"(mw) : "memory");
}

// ---------------- DistMult decoder ----------------
__global__ void __launch_bounds__(256) k_decode(const int* __restrict__ src,
                                                const int* __restrict__ dst,
                                                const int* __restrict__ et,
                                                const float* __restrict__ rel,
                                                float* __restrict__ out)
{
    int e = (blockIdx.x * blockDim.x + threadIdx.x) >> 5;
    int lane = threadIdx.x & 31;
    if (e >= NEDGE) return;
    int s = src[e], d = dst[e], t = et[e];
    float4 a = *(const float4*)&g_h2[(long long)s * DIM + lane * 4];
    float4 b = *(const float4*)&g_h2[(long long)d * DIM + lane * 4];
    float4 r = *(const float4*)&rel[t * DIM + lane * 4];
    float dot = a.x * r.x * b.x + a.y * r.y * b.y + a.z * r.z * b.z + a.w * r.w * b.w;
#pragma unroll
    for (int o = 16; o > 0; o >>= 1) dot += __shfl_xor_sync(0xffffffffu, dot, o);
    if (lane == 0) out[e] = dot;
}

__global__ void k_penalty(const float* __restrict__ rel, float* __restrict__ out, int idx)
{
    __shared__ float red[8];
    float s = 0.f;
    for (int i = threadIdx.x; i < R2 * DIM; i += 256) { float v = rel[i]; s += v * v; }
#pragma unroll
    for (int o = 16; o > 0; o >>= 1) s += __shfl_xor_sync(0xffffffffu, s, o);
    if ((threadIdx.x & 31) == 0) red[threadIdx.x >> 5] = s;
    __syncthreads();
    if (threadIdx.x < 8) {
        s = red[threadIdx.x];
#pragma unroll
        for (int o = 4; o > 0; o >>= 1) s += __shfl_xor_sync(0x000000ffu, s, o);
        if (threadIdx.x == 0) out[idx] = s;
    }
}

extern "C" void kernel_launch(void* const* d_in, const int* in_sizes, int n_in,
                              void* d_out, int out_size)
{
    const int* edge_index = (const int*)d_in[0];
    const int* src = edge_index;
    const int* dst = edge_index + NEDGE;
    const int* et  = (const int*)d_in[1];
    const float* emb    = (const float*)d_in[2];
    const float* ebias  = (const float*)d_in[3];
    const float* bases1 = (const float*)d_in[4];
    const float* comp1  = (const float*)d_in[5];
    const float* root1  = (const float*)d_in[6];
    const float* bias1  = (const float*)d_in[7];
    const float* bases2 = (const float*)d_in[8];
    const float* comp2  = (const float*)d_in[9];
    const float* root2  = (const float*)d_in[10];
    const float* bias2  = (const float*)d_in[11];
    const float* rel    = (const float*)d_in[12];
    float* out = (float*)d_out;

    static bool attr_done = false;
    if (!attr_done) {
        cudaFuncSetAttribute(k_gemm_mma<0>, cudaFuncAttributeMaxDynamicSharedMemorySize, 196608);
        cudaFuncSetAttribute(k_gemm_mma<1>, cudaFuncAttributeMaxDynamicSharedMemorySize, 196608);
        attr_done = true;
    }

    k_zero_counts<<<(N_ENT * R2 + 255) / 256, 256>>>();
    k_hist<<<(NEDGE + 255) / 256, 256>>>(dst, et);

    const int ngrid = (N_ENT + 127) / 128;   // 782

    k_build_wt<<<(WCOLS * DIM + 255) / 256, 256>>>(bases1, root1);
    k_gemm_mma<0><<<ngrid, 256, 196608>>>(emb, ebias, bias1);
    k_edge<0><<<NEDGE / 8, 256>>>(src, dst, et, comp1);

    k_build_wt<<<(WCOLS * DIM + 255) / 256, 256>>>(bases2, root2);
    k_gemm_mma<1><<<ngrid, 256, 196608>>>(emb, nullptr, bias2);
    k_edge<1><<<NEDGE / 8, 256>>>(src, dst, et, comp2);

    k_decode<<<NEDGE / 8, 256>>>(src, dst, et, rel, out);
    if (out_size > NEDGE)
        k_penalty<<<1, 256>>>(rel, out, out_size - 1);
}

// round 7
// speedup vs baseline: 2.3528x; 1.0064x over previous
#include <cuda_runtime.h>
#include <cuda_bf16.h>
#include <cuda_fp16.h>
#include <cstdint>

#define N_ENT  100000
#define DIM    128
#define R2     100
#define NBASES 4
#define NEDGE  400000
#define WCOLS  640

// ---- scratch (device globals; no allocation allowed) ----
__device__ __align__(16) int    g_counts[N_ENT * R2];               // 40 MB
__device__ __align__(16) __half g_xb_h[(size_t)N_ENT * 512];        // 102.4 MB
__device__ __align__(16) float  g_h1[N_ENT * DIM];                  // 51.2 MB
__device__ __align__(16) float  g_h2[N_ENT * DIM];                  // 51.2 MB
// pre-swizzled W^T tiles: 5 tiles of [128 rows(N) x 128 cols(K)] bf16, hi/lo split
__device__ __align__(1024) unsigned char g_wt_hi[5 * 32768];
__device__ __align__(1024) unsigned char g_wt_lo[5 * 32768];

// blocked K-major SW128 layout for a 128x128 bf16 tile
__device__ __host__ __forceinline__ uint32_t tile_off(int row, int col) {
    uint32_t b = ((uint32_t)(row >> 3) << 10) + ((uint32_t)(col >> 6) << 14)
               + ((uint32_t)(row & 7) << 7) + ((uint32_t)(col & 63) << 1);
    return b ^ ((b >> 3) & 0x70);
}

__device__ __forceinline__ uint32_t smem_u32(const void* p) {
    uint32_t a;
    asm("{ .reg .u64 t; cvta.to.shared.u64 t, %1; cvt.u32.u64 %0, t; }" : "=r"(a) : "l"(p));
    return a;
}

__device__ __forceinline__ void ldsm4(uint32_t* r, uint32_t addr) {
    asm volatile("ldmatrix.sync.aligned.m8n8.x4.shared.b16 {%0,%1,%2,%3}, [%4];"
                 : "=r"(r[0]), "=r"(r[1]), "=r"(r[2]), "=r"(r[3]) : "r"(addr));
}

__device__ __forceinline__ void mma16816(float* d, const uint32_t* a, const uint32_t* b) {
    asm volatile("mma.sync.aligned.m16n8k16.row.col.f32.bf16.bf16.f32 "
                 "{%0,%1,%2,%3}, {%4,%5,%6,%7}, {%8,%9}, {%0,%1,%2,%3};"
                 : "+f"(d[0]), "+f"(d[1]), "+f"(d[2]), "+f"(d[3])
                 : "r"(a[0]), "r"(a[1]), "r"(a[2]), "r"(a[3]), "r"(b[0]), "r"(b[1]));
}

// async-copy one W tile (hi+lo, 64KB) into smem buffer `buf`
__device__ __forceinline__ void cp_w_tile(uint32_t sb, int nt, int buf, int tid) {
    const uint4* sh = (const uint4*)(g_wt_hi + nt * 32768) + tid;
    const uint4* sl = (const uint4*)(g_wt_lo + nt * 32768) + tid;
    uint32_t dh = sb + 65536 + (uint32_t)buf * 65536 + (uint32_t)tid * 16;
    uint32_t dl = dh + 32768;
#pragma unroll
    for (int i = 0; i < 8; i++) {
        asm volatile("cp.async.cg.shared.global [%0], [%1], 16;"
                     :: "r"(dh + i * 4096), "l"(sh + i * 256));
        asm volatile("cp.async.cg.shared.global [%0], [%1], 16;"
                     :: "r"(dl + i * 4096), "l"(sl + i * 256));
    }
    asm volatile("cp.async.commit_group;");
}

// ---------------- norm precompute ----------------
__global__ void k_zero_counts() {
    int i = blockIdx.x * blockDim.x + threadIdx.x;
    if (i < N_ENT * R2) g_counts[i] = 0;
}
__global__ void k_hist(const int* __restrict__ dst, const int* __restrict__ et) {
    int e = blockIdx.x * blockDim.x + threadIdx.x;
    if (e < NEDGE) atomicAdd(&g_counts[dst[e] * R2 + et[e]], 1);
}

// ---------------- build pre-swizzled W^T hi/lo tiles ----------------
__global__ void k_build_wt(const float* __restrict__ bases, const float* __restrict__ root) {
    int idx = blockIdx.x * blockDim.x + threadIdx.x;   // 640*128
    if (idx >= WCOLS * DIM) return;
    int c = idx >> 7;     // output column 0..639 (= W^T row n)
    int k = idx & 127;    // K index
    float v;
    if (c < 512) {
        int b = c >> 7, h = c & 127;
        v = bases[(b * DIM + k) * DIM + h];   // bases[b, k, h]
    } else {
        v = root[k * DIM + (c - 512)];
    }
    __nv_bfloat16 hh = __float2bfloat16(v);
    __nv_bfloat16 ll = __float2bfloat16(v - __bfloat162float(hh));
    int nt = (c < 512) ? (c >> 7) : 4;
    int rt = c & 127;
    uint32_t off = tile_off(rt, k);
    *(unsigned short*)(g_wt_hi + nt * 32768 + off) = __bfloat16_as_ushort(hh);
    *(unsigned short*)(g_wt_lo + nt * 32768 + off) = __bfloat16_as_ushort(ll);
}

// ---------------- HMMA GEMM: act(X)[128 rows x 128] @ W[128x640] ----------------
// grid = 782 row-blocks; per CTA: stage A once, loop over 5 W tiles with
// cp.async double buffering. split-bf16: D = Ah*Wh + Ah*Wl + Al*Wh.
// smem: A_hi[32K] A_lo[32K] | W buf0 hi/lo [64K] | W buf1 hi/lo [64K] = 192KB
template<int MODE>
__global__ void __launch_bounds__(256, 1) k_gemm_mma(const float* __restrict__ Xp,
                                                     const float* __restrict__ inb,
                                                     const float* __restrict__ outb)
{
    extern __shared__ unsigned char smem[];
    const uint32_t sb = smem_u32(smem);
    const float* __restrict__ X = (MODE == 0) ? Xp : (const float*)g_h1;

    const int tid  = threadIdx.x;
    const int lane = tid & 31;
    const int wid  = tid >> 5;
    const int row0 = blockIdx.x * 128;

    // kick off W tile 0 prefetch first
    cp_w_tile(sb, 0, 0, tid);

    // ---- stage A tile: fp32 -> (+bias) -> relu -> bf16 hi/lo, swizzled ----
    {
        const int row = tid >> 1;
        const int colbase = (tid & 1) * 64;
        const int gr = row0 + row;
        const bool ok = gr < N_ENT;
        const uint32_t C = ((uint32_t)(row >> 3) << 10) + ((uint32_t)(row & 7) << 7);
        const uint32_t swz = (uint32_t)(row & 7) << 4;
#pragma unroll
        for (int j = 0; j < 16; j++) {
            const int col = colbase + j * 4;
            float4 v = ok ? *(const float4*)(X + (size_t)gr * DIM + col)
                          : make_float4(0.f, 0.f, 0.f, 0.f);
            if (MODE == 0 && ok) {
                float4 b = *(const float4*)(inb + col);
                v.x += b.x; v.y += b.y; v.z += b.z; v.w += b.w;
            }
            v.x = fmaxf(v.x, 0.f); v.y = fmaxf(v.y, 0.f);
            v.z = fmaxf(v.z, 0.f); v.w = fmaxf(v.w, 0.f);
            __nv_bfloat16 h0 = __float2bfloat16(v.x), h1 = __float2bfloat16(v.y);
            __nv_bfloat16 h2 = __float2bfloat16(v.z), h3 = __float2bfloat16(v.w);
            __nv_bfloat16 l0 = __float2bfloat16(v.x - __bfloat162float(h0));
            __nv_bfloat16 l1 = __float2bfloat16(v.y - __bfloat162float(h1));
            __nv_bfloat16 l2 = __float2bfloat16(v.z - __bfloat162float(h2));
            __nv_bfloat16 l3 = __float2bfloat16(v.w - __bfloat162float(h3));
            uint2 hp, lp;
            hp.x = (uint32_t)__bfloat16_as_ushort(h0) | ((uint32_t)__bfloat16_as_ushort(h1) << 16);
            hp.y = (uint32_t)__bfloat16_as_ushort(h2) | ((uint32_t)__bfloat16_as_ushort(h3) << 16);
            lp.x = (uint32_t)__bfloat16_as_ushort(l0) | ((uint32_t)__bfloat16_as_ushort(l1) << 16);
            lp.y = (uint32_t)__bfloat16_as_ushort(l2) | ((uint32_t)__bfloat16_as_ushort(l3) << 16);
            const uint32_t cp = ((uint32_t)(col >> 6) << 14) + ((uint32_t)(col & 63) << 1);
            const uint32_t off = (C + cp) ^ swz;
            *(uint2*)(smem + off)         = hp;
            *(uint2*)(smem + 32768 + off) = lp;
        }
    }

    // ---- per-warp fragment address precompute ----
    const int wm = wid & 1;
    const int wn = wid >> 1;
    const uint32_t swz = (uint32_t)(lane & 7) << 4;
    const uint32_t koffA = (uint32_t)(lane & 16) >> 1;
    const uint32_t koffB = (uint32_t)(lane & 8);
    uint32_t preA[4], preBoff[2];
#pragma unroll
    for (int mi = 0; mi < 4; mi++) {
        int r = wm * 64 + mi * 16 + (lane & 15);
        preA[mi] = sb + (((uint32_t)(r >> 3) << 10) + ((uint32_t)(r & 7) << 7));
    }
#pragma unroll
    for (int nj = 0; nj < 2; nj++) {
        int r = wn * 32 + nj * 16 + ((lane & 16) >> 1) + (lane & 7);
        preBoff[nj] = ((uint32_t)(r >> 3) << 10) + ((uint32_t)(r & 7) << 7);
    }

    float* agg = (MODE == 0) ? g_h1 : g_h2;

    for (int nt = 0; nt < 5; nt++) {
        if (nt < 4) {
            cp_w_tile(sb, nt + 1, (nt + 1) & 1, tid);
            asm volatile("cp.async.wait_group 1;" ::: "memory");
        } else {
            asm volatile("cp.async.wait_group 0;" ::: "memory");
        }
        __syncthreads();   // W tile nt ready; (iter 0: also publishes A stores)

        const uint32_t wbase = sb + 65536 + (uint32_t)(nt & 1) * 65536;
        uint32_t preB[2] = { wbase + preBoff[0], wbase + preBoff[1] };

        float acc[4][4][4];
#pragma unroll
        for (int mi = 0; mi < 4; mi++)
#pragma unroll
            for (int ni = 0; ni < 4; ni++)
#pragma unroll
                for (int q = 0; q < 4; q++) acc[mi][ni][q] = 0.f;

#pragma unroll
        for (int kk = 0; kk < 8; kk++) {
            const int k = kk * 16;
            const uint32_t colA = k + koffA;
            const uint32_t colB = k + koffB;
            const uint32_t cpA = ((colA & 64) << 8) + ((colA & 63) << 1);
            const uint32_t cpB = ((colB & 64) << 8) + ((colB & 63) << 1);

            uint32_t ah[4][4], wh[4][2], wl[4][2];
#pragma unroll
            for (int mi = 0; mi < 4; mi++)
                ldsm4(ah[mi], (preA[mi] + cpA) ^ swz);
#pragma unroll
            for (int nj = 0; nj < 2; nj++) {
                uint32_t t[4];
                ldsm4(t, (preB[nj] + cpB) ^ swz);
                wh[2 * nj][0] = t[0]; wh[2 * nj][1] = t[1];
                wh[2 * nj + 1][0] = t[2]; wh[2 * nj + 1][1] = t[3];
            }
#pragma unroll
            for (int nj = 0; nj < 2; nj++) {
                uint32_t t[4];
                ldsm4(t, (preB[nj] + 32768 + cpB) ^ swz);
                wl[2 * nj][0] = t[0]; wl[2 * nj][1] = t[1];
                wl[2 * nj + 1][0] = t[2]; wl[2 * nj + 1][1] = t[3];
            }
            // Ah*Wh
#pragma unroll
            for (int mi = 0; mi < 4; mi++)
#pragma unroll
                for (int ni = 0; ni < 4; ni++)
                    mma16816(acc[mi][ni], ah[mi], wh[ni]);
            // Ah*Wl
#pragma unroll
            for (int mi = 0; mi < 4; mi++)
#pragma unroll
                for (int ni = 0; ni < 4; ni++)
                    mma16816(acc[mi][ni], ah[mi], wl[ni]);
            // Al*Wh
#pragma unroll
            for (int mi = 0; mi < 4; mi++)
                ldsm4(ah[mi], (preA[mi] + 32768 + cpA) ^ swz);
#pragma unroll
            for (int mi = 0; mi < 4; mi++)
#pragma unroll
                for (int ni = 0; ni < 4; ni++)
                    mma16816(acc[mi][ni], ah[mi], wh[ni]);
        }

        // ---- epilogue for this nt ----
#pragma unroll
        for (int mi = 0; mi < 4; mi++) {
            const int gr0 = row0 + wm * 64 + mi * 16 + (lane >> 2);
#pragma unroll
            for (int half = 0; half < 2; half++) {
                const int gr = gr0 + half * 8;
                if (gr >= N_ENT) continue;
#pragma unroll
                for (int ni = 0; ni < 4; ni++) {
                    const int n = wn * 32 + ni * 8 + (lane & 3) * 2;
                    float2 o;
                    o.x = acc[mi][ni][half * 2 + 0];
                    o.y = acc[mi][ni][half * 2 + 1];
                    if (nt < 4) {
                        *(__half2*)(g_xb_h + (size_t)gr * 512 + nt * 128 + n) =
                            __float22half2_rn(o);
                    } else {
                        float2 b = *(const float2*)(outb + n);
                        o.x += b.x; o.y += b.y;
                        *(float2*)(agg + (size_t)gr * DIM + n) = o;
                    }
                }
            }
        }
        __syncthreads();   // all warps done with buffer before it is overwritten
    }
}

// ---------------- edge pass: mix basis projections (fp16 xb), scatter-add ----------------
__device__ __forceinline__ float4 ld_xb4(const __half* p) {
    uint2 u = *(const uint2*)p;
    __half2 a = *reinterpret_cast<__half2*>(&u.x);
    __half2 b = *reinterpret_cast<__half2*>(&u.y);
    float2 fa = __half22float2(a), fb = __half22float2(b);
    return make_float4(fa.x, fa.y, fb.x, fb.y);
}

template<int LAYER>
__global__ void __launch_bounds__(256) k_edge(const int* __restrict__ src,
                                              const int* __restrict__ dst,
                                              const int* __restrict__ et,
                                              const float* __restrict__ comp)
{
    int e = (blockIdx.x * blockDim.x + threadIdx.x) >> 5;
    int lane = threadIdx.x & 31;
    if (e >= NEDGE) return;
    int s = src[e], d = dst[e], t = et[e];
    float norm = 1.0f / fmaxf((float)g_counts[d * R2 + t], 1.0f);
    float c0 = comp[t * 4 + 0] * norm;
    float c1 = comp[t * 4 + 1] * norm;
    float c2 = comp[t * 4 + 2] * norm;
    float c3 = comp[t * 4 + 3] * norm;
    const __half* xb = g_xb_h + (size_t)s * 512 + lane * 4;
    float4 v0 = ld_xb4(xb);
    float4 v1 = ld_xb4(xb + 128);
    float4 v2 = ld_xb4(xb + 256);
    float4 v3 = ld_xb4(xb + 384);
    float mx = c0 * v0.x + c1 * v1.x + c2 * v2.x + c3 * v3.x;
    float my = c0 * v0.y + c1 * v1.y + c2 * v2.y + c3 * v3.y;
    float mz = c0 * v0.z + c1 * v1.z + c2 * v2.z + c3 * v3.z;
    float mw = c0 * v0.w + c1 * v1.w + c2 * v2.w + c3 * v3.w;
    float* agg = (LAYER == 0) ? g_h1 : g_h2;
    float* p = agg + d * DIM + lane * 4;
    asm volatile("red.global.add.v4.f32 [%0], {%1,%2,%3,%4};"
                 :: "l"(p), "f"(mx), "f"(my), "f"(mz), "f"(mw) : "memory");
}

// ---------------- DistMult decoder ----------------
__global__ void __launch_bounds__(256) k_decode(const int* __restrict__ src,
                                                const int* __restrict__ dst,
                                                const int* __restrict__ et,
                                                const float* __restrict__ rel,
                                                float* __restrict__ out)
{
    int e = (blockIdx.x * blockDim.x + threadIdx.x) >> 5;
    int lane = threadIdx.x & 31;
    if (e >= NEDGE) return;
    int s = src[e], d = dst[e], t = et[e];
    float4 a = *(const float4*)&g_h2[(long long)s * DIM + lane * 4];
    float4 b = *(const float4*)&g_h2[(long long)d * DIM + lane * 4];
    float4 r = *(const float4*)&rel[t * DIM + lane * 4];
    float dot = a.x * r.x * b.x + a.y * r.y * b.y + a.z * r.z * b.z + a.w * r.w * b.w;
#pragma unroll
    for (int o = 16; o > 0; o >>= 1) dot += __shfl_xor_sync(0xffffffffu, dot, o);
    if (lane == 0) out[e] = dot;
}

__global__ void k_penalty(const float* __restrict__ rel, float* __restrict__ out, int idx)
{
    __shared__ float red[8];
    float s = 0.f;
    for (int i = threadIdx.x; i < R2 * DIM; i += 256) { float v = rel[i]; s += v * v; }
#pragma unroll
    for (int o = 16; o > 0; o >>= 1) s += __shfl_xor_sync(0xffffffffu, s, o);
    if ((threadIdx.x & 31) == 0) red[threadIdx.x >> 5] = s;
    __syncthreads();
    if (threadIdx.x < 8) {
        s = red[threadIdx.x];
#pragma unroll
        for (int o = 4; o > 0; o >>= 1) s += __shfl_xor_sync(0x000000ffu, s, o);
        if (threadIdx.x == 0) out[idx] = s;
    }
}

extern "C" void kernel_launch(void* const* d_in, const int* in_sizes, int n_in,
                              void* d_out, int out_size)
{
    const int* edge_index = (const int*)d_in[0];
    const int* src = edge_index;
    const int* dst = edge_index + NEDGE;
    const int* et  = (const int*)d_in[1];
    const float* emb    = (const float*)d_in[2];
    const float* ebias  = (const float*)d_in[3];
    const float* bases1 = (const float*)d_in[4];
    const float* comp1  = (const float*)d_in[5];
    const float* root1  = (const float*)d_in[6];
    const float* bias1  = (const float*)d_in[7];
    const float* bases2 = (const float*)d_in[8];
    const float* comp2  = (const float*)d_in[9];
    const float* root2  = (const float*)d_in[10];
    const float* bias2  = (const float*)d_in[11];
    const float* rel    = (const float*)d_in[12];
    float* out = (float*)d_out;

    static bool attr_done = false;
    if (!attr_done) {
        cudaFuncSetAttribute(k_gemm_mma<0>, cudaFuncAttributeMaxDynamicSharedMemorySize, 196608);
        cudaFuncSetAttribute(k_gemm_mma<1>, cudaFuncAttributeMaxDynamicSharedMemorySize, 196608);
        attr_done = true;
    }

    k_zero_counts<<<(N_ENT * R2 + 255) / 256, 256>>>();
    k_hist<<<(NEDGE + 255) / 256, 256>>>(dst, et);

    const int ngrid = (N_ENT + 127) / 128;   // 782

    k_build_wt<<<(WCOLS * DIM + 255) / 256, 256>>>(bases1, root1);
    k_gemm_mma<0><<<ngrid, 256, 196608>>>(emb, ebias, bias1);
    k_edge<0><<<NEDGE / 8, 256>>>(src, dst, et, comp1);

    k_build_wt<<<(WCOLS * DIM + 255) / 256, 256>>>(bases2, root2);
    k_gemm_mma<1><<<ngrid, 256, 196608>>>(emb, nullptr, bias2);
    k_edge<1><<<NEDGE / 8, 256>>>(src, dst, et, comp2);

    k_decode<<<NEDGE / 8, 256>>>(src, dst, et, rel, out);
    if (out_size > NEDGE)
        k_penalty<<<1, 256>>>(rel, out, out_size - 1);
}

// round 8
// speedup vs baseline: 2.3547x; 1.0008x over previous
#include <cuda_runtime.h>
#include <cuda_bf16.h>
#include <cuda_fp16.h>
#include <cstdint>

#define N_ENT  100000
#define DIM    128
#define R2     100
#define NBASES 4
#define NEDGE  400000
#define WCOLS  640

// ---- scratch (device globals; no allocation allowed) ----
__device__ __align__(16) int    g_counts[N_ENT * R2];               // 40 MB
__device__ __align__(16) __half g_xb_h[(size_t)N_ENT * 512];        // 102.4 MB
__device__ __align__(16) float  g_h1[N_ENT * DIM];                  // 51.2 MB
__device__ __align__(16) float  g_h2[N_ENT * DIM];                  // 51.2 MB
// pre-swizzled W^T tiles: 5 tiles of [128 rows(N) x 128 cols(K)] bf16, hi/lo split
__device__ __align__(1024) unsigned char g_wt_hi[5 * 32768];
__device__ __align__(1024) unsigned char g_wt_lo[5 * 32768];

// blocked K-major SW128 layout for a 128x128 bf16 tile
__device__ __host__ __forceinline__ uint32_t tile_off(int row, int col) {
    uint32_t b = ((uint32_t)(row >> 3) << 10) + ((uint32_t)(col >> 6) << 14)
               + ((uint32_t)(row & 7) << 7) + ((uint32_t)(col & 63) << 1);
    return b ^ ((b >> 3) & 0x70);
}

__device__ __forceinline__ uint32_t smem_u32(const void* p) {
    uint32_t a;
    asm("{ .reg .u64 t; cvta.to.shared.u64 t, %1; cvt.u32.u64 %0, t; }" : "=r"(a) : "l"(p));
    return a;
}

__device__ __forceinline__ void ldsm4(uint32_t* r, uint32_t addr) {
    asm volatile("ldmatrix.sync.aligned.m8n8.x4.shared.b16 {%0,%1,%2,%3}, [%4];"
                 : "=r"(r[0]), "=r"(r[1]), "=r"(r[2]), "=r"(r[3]) : "r"(addr));
}

__device__ __forceinline__ void mma16816(float* d, const uint32_t* a, const uint32_t* b) {
    asm volatile("mma.sync.aligned.m16n8k16.row.col.f32.bf16.bf16.f32 "
                 "{%0,%1,%2,%3}, {%4,%5,%6,%7}, {%8,%9}, {%0,%1,%2,%3};"
                 : "+f"(d[0]), "+f"(d[1]), "+f"(d[2]), "+f"(d[3])
                 : "r"(a[0]), "r"(a[1]), "r"(a[2]), "r"(a[3]), "r"(b[0]), "r"(b[1]));
}

// async-copy one W tile (hi+lo, 64KB) into smem buffer `buf`
__device__ __forceinline__ void cp_w_tile(uint32_t sb, int nt, int buf, int tid) {
    const uint4* sh = (const uint4*)(g_wt_hi + nt * 32768) + tid;
    const uint4* sl = (const uint4*)(g_wt_lo + nt * 32768) + tid;
    uint32_t dh = sb + 65536 + (uint32_t)buf * 65536 + (uint32_t)tid * 16;
    uint32_t dl = dh + 32768;
#pragma unroll
    for (int i = 0; i < 8; i++) {
        asm volatile("cp.async.cg.shared.global [%0], [%1], 16;"
                     :: "r"(dh + i * 4096), "l"(sh + i * 256));
        asm volatile("cp.async.cg.shared.global [%0], [%1], 16;"
                     :: "r"(dl + i * 4096), "l"(sl + i * 256));
    }
    asm volatile("cp.async.commit_group;");
}

// ---------------- norm precompute ----------------
__global__ void k_zero_counts() {
    int i = blockIdx.x * blockDim.x + threadIdx.x;
    if (i < N_ENT * R2) g_counts[i] = 0;
}
__global__ void k_hist(const int* __restrict__ dst, const int* __restrict__ et) {
    int e = blockIdx.x * blockDim.x + threadIdx.x;
    if (e < NEDGE) atomicAdd(&g_counts[dst[e] * R2 + et[e]], 1);
}

// ---------------- build pre-swizzled W^T hi/lo tiles ----------------
__global__ void k_build_wt(const float* __restrict__ bases, const float* __restrict__ root) {
    int idx = blockIdx.x * blockDim.x + threadIdx.x;   // 640*128
    if (idx >= WCOLS * DIM) return;
    int c = idx >> 7;     // output column 0..639 (= W^T row n)
    int k = idx & 127;    // K index
    float v;
    if (c < 512) {
        int b = c >> 7, h = c & 127;
        v = bases[(b * DIM + k) * DIM + h];   // bases[b, k, h]
    } else {
        v = root[k * DIM + (c - 512)];
    }
    __nv_bfloat16 hh = __float2bfloat16(v);
    __nv_bfloat16 ll = __float2bfloat16(v - __bfloat162float(hh));
    int nt = (c < 512) ? (c >> 7) : 4;
    int rt = c & 127;
    uint32_t off = tile_off(rt, k);
    *(unsigned short*)(g_wt_hi + nt * 32768 + off) = __bfloat16_as_ushort(hh);
    *(unsigned short*)(g_wt_lo + nt * 32768 + off) = __bfloat16_as_ushort(ll);
}

// ---------------- HMMA GEMM: act(X)[128 rows x 128] @ W[128x640] ----------------
// grid = 782 row-blocks; per CTA: stage A once, loop over 5 W tiles with
// cp.async double buffering. split-bf16: D = Ah*Wh + Ah*Wl + Al*Wh.
// smem: A_hi[32K] A_lo[32K] | W buf0 hi/lo [64K] | W buf1 hi/lo [64K] = 192KB
template<int MODE>
__global__ void __launch_bounds__(256, 1) k_gemm_mma(const float* __restrict__ Xp,
                                                     const float* __restrict__ inb,
                                                     const float* __restrict__ outb)
{
    extern __shared__ unsigned char smem[];
    const uint32_t sb = smem_u32(smem);
    const float* __restrict__ X = (MODE == 0) ? Xp : (const float*)g_h1;

    const int tid  = threadIdx.x;
    const int lane = tid & 31;
    const int wid  = tid >> 5;
    const int row0 = blockIdx.x * 128;

    // kick off W tile 0 prefetch first
    cp_w_tile(sb, 0, 0, tid);

    // ---- stage A tile: fp32 -> (+bias) -> relu -> bf16 hi/lo, swizzled ----
    {
        const int row = tid >> 1;
        const int colbase = (tid & 1) * 64;
        const int gr = row0 + row;
        const bool ok = gr < N_ENT;
        const uint32_t C = ((uint32_t)(row >> 3) << 10) + ((uint32_t)(row & 7) << 7);
        const uint32_t swz = (uint32_t)(row & 7) << 4;
#pragma unroll
        for (int j = 0; j < 16; j++) {
            const int col = colbase + j * 4;
            float4 v = ok ? *(const float4*)(X + (size_t)gr * DIM + col)
                          : make_float4(0.f, 0.f, 0.f, 0.f);
            if (MODE == 0 && ok) {
                float4 b = *(const float4*)(inb + col);
                v.x += b.x; v.y += b.y; v.z += b.z; v.w += b.w;
            }
            v.x = fmaxf(v.x, 0.f); v.y = fmaxf(v.y, 0.f);
            v.z = fmaxf(v.z, 0.f); v.w = fmaxf(v.w, 0.f);
            __nv_bfloat16 h0 = __float2bfloat16(v.x), h1 = __float2bfloat16(v.y);
            __nv_bfloat16 h2 = __float2bfloat16(v.z), h3 = __float2bfloat16(v.w);
            __nv_bfloat16 l0 = __float2bfloat16(v.x - __bfloat162float(h0));
            __nv_bfloat16 l1 = __float2bfloat16(v.y - __bfloat162float(h1));
            __nv_bfloat16 l2 = __float2bfloat16(v.z - __bfloat162float(h2));
            __nv_bfloat16 l3 = __float2bfloat16(v.w - __bfloat162float(h3));
            uint2 hp, lp;
            hp.x = (uint32_t)__bfloat16_as_ushort(h0) | ((uint32_t)__bfloat16_as_ushort(h1) << 16);
            hp.y = (uint32_t)__bfloat16_as_ushort(h2) | ((uint32_t)__bfloat16_as_ushort(h3) << 16);
            lp.x = (uint32_t)__bfloat16_as_ushort(l0) | ((uint32_t)__bfloat16_as_ushort(l1) << 16);
            lp.y = (uint32_t)__bfloat16_as_ushort(l2) | ((uint32_t)__bfloat16_as_ushort(l3) << 16);
            const uint32_t cp = ((uint32_t)(col >> 6) << 14) + ((uint32_t)(col & 63) << 1);
            const uint32_t off = (C + cp) ^ swz;
            *(uint2*)(smem + off)         = hp;
            *(uint2*)(smem + 32768 + off) = lp;
        }
    }

    // ---- per-warp fragment address precompute ----
    const int wm = wid & 1;
    const int wn = wid >> 1;
    const uint32_t swz = (uint32_t)(lane & 7) << 4;
    const uint32_t koffA = (uint32_t)(lane & 16) >> 1;
    const uint32_t koffB = (uint32_t)(lane & 8);
    uint32_t preA[4], preBoff[2];
#pragma unroll
    for (int mi = 0; mi < 4; mi++) {
        int r = wm * 64 + mi * 16 + (lane & 15);
        preA[mi] = sb + (((uint32_t)(r >> 3) << 10) + ((uint32_t)(r & 7) << 7));
    }
#pragma unroll
    for (int nj = 0; nj < 2; nj++) {
        int r = wn * 32 + nj * 16 + ((lane & 16) >> 1) + (lane & 7);
        preBoff[nj] = ((uint32_t)(r >> 3) << 10) + ((uint32_t)(r & 7) << 7);
    }

    float* agg = (MODE == 0) ? g_h1 : g_h2;

    for (int nt = 0; nt < 5; nt++) {
        if (nt < 4) {
            cp_w_tile(sb, nt + 1, (nt + 1) & 1, tid);
            asm volatile("cp.async.wait_group 1;" ::: "memory");
        } else {
            asm volatile("cp.async.wait_group 0;" ::: "memory");
        }
        __syncthreads();   // W tile nt ready; (iter 0: also publishes A stores)

        const uint32_t wbase = sb + 65536 + (uint32_t)(nt & 1) * 65536;
        uint32_t preB[2] = { wbase + preBoff[0], wbase + preBoff[1] };

        float acc[4][4][4];
#pragma unroll
        for (int mi = 0; mi < 4; mi++)
#pragma unroll
            for (int ni = 0; ni < 4; ni++)
#pragma unroll
                for (int q = 0; q < 4; q++) acc[mi][ni][q] = 0.f;

#pragma unroll
        for (int kk = 0; kk < 8; kk++) {
            const int k = kk * 16;
            const uint32_t colA = k + koffA;
            const uint32_t colB = k + koffB;
            const uint32_t cpA = ((colA & 64) << 8) + ((colA & 63) << 1);
            const uint32_t cpB = ((colB & 64) << 8) + ((colB & 63) << 1);

            uint32_t ah[4][4], wh[4][2], wl[4][2];
#pragma unroll
            for (int mi = 0; mi < 4; mi++)
                ldsm4(ah[mi], (preA[mi] + cpA) ^ swz);
#pragma unroll
            for (int nj = 0; nj < 2; nj++) {
                uint32_t t[4];
                ldsm4(t, (preB[nj] + cpB) ^ swz);
                wh[2 * nj][0] = t[0]; wh[2 * nj][1] = t[1];
                wh[2 * nj + 1][0] = t[2]; wh[2 * nj + 1][1] = t[3];
            }
#pragma unroll
            for (int nj = 0; nj < 2; nj++) {
                uint32_t t[4];
                ldsm4(t, (preB[nj] + 32768 + cpB) ^ swz);
                wl[2 * nj][0] = t[0]; wl[2 * nj][1] = t[1];
                wl[2 * nj + 1][0] = t[2]; wl[2 * nj + 1][1] = t[3];
            }
            // Ah*Wh
#pragma unroll
            for (int mi = 0; mi < 4; mi++)
#pragma unroll
                for (int ni = 0; ni < 4; ni++)
                    mma16816(acc[mi][ni], ah[mi], wh[ni]);
            // Ah*Wl
#pragma unroll
            for (int mi = 0; mi < 4; mi++)
#pragma unroll
                for (int ni = 0; ni < 4; ni++)
                    mma16816(acc[mi][ni], ah[mi], wl[ni]);
            // Al*Wh
#pragma unroll
            for (int mi = 0; mi < 4; mi++)
                ldsm4(ah[mi], (preA[mi] + 32768 + cpA) ^ swz);
#pragma unroll
            for (int mi = 0; mi < 4; mi++)
#pragma unroll
                for (int ni = 0; ni < 4; ni++)
                    mma16816(acc[mi][ni], ah[mi], wh[ni]);
        }

        // ---- epilogue for this nt ----
#pragma unroll
        for (int mi = 0; mi < 4; mi++) {
            const int gr0 = row0 + wm * 64 + mi * 16 + (lane >> 2);
#pragma unroll
            for (int half = 0; half < 2; half++) {
                const int gr = gr0 + half * 8;
                if (gr >= N_ENT) continue;
#pragma unroll
                for (int ni = 0; ni < 4; ni++) {
                    const int n = wn * 32 + ni * 8 + (lane & 3) * 2;
                    float2 o;
                    o.x = acc[mi][ni][half * 2 + 0];
                    o.y = acc[mi][ni][half * 2 + 1];
                    if (nt < 4) {
                        *(__half2*)(g_xb_h + (size_t)gr * 512 + nt * 128 + n) =
                            __float22half2_rn(o);
                    } else {
                        float2 b = *(const float2*)(outb + n);
                        o.x += b.x; o.y += b.y;
                        *(float2*)(agg + (size_t)gr * DIM + n) = o;
                    }
                }
            }
        }
        __syncthreads();   // all warps done with buffer before it is overwritten
    }
}

// ---------------- edge pass: mix basis projections (fp16 xb), scatter-add ----------------
__device__ __forceinline__ float4 ld_xb4(const __half* p) {
    uint2 u = *(const uint2*)p;
    __half2 a = *reinterpret_cast<__half2*>(&u.x);
    __half2 b = *reinterpret_cast<__half2*>(&u.y);
    float2 fa = __half22float2(a), fb = __half22float2(b);
    return make_float4(fa.x, fa.y, fb.x, fb.y);
}

template<int LAYER>
__global__ void __launch_bounds__(256) k_edge(const int* __restrict__ src,
                                              const int* __restrict__ dst,
                                              const int* __restrict__ et,
                                              const float* __restrict__ comp)
{
    int e = (blockIdx.x * blockDim.x + threadIdx.x) >> 5;
    int lane = threadIdx.x & 31;
    if (e >= NEDGE) return;
    int s = src[e], d = dst[e], t = et[e];
    float norm = 1.0f / fmaxf((float)g_counts[d * R2 + t], 1.0f);
    float c0 = comp[t * 4 + 0] * norm;
    float c1 = comp[t * 4 + 1] * norm;
    float c2 = comp[t * 4 + 2] * norm;
    float c3 = comp[t * 4 + 3] * norm;
    const __half* xb = g_xb_h + (size_t)s * 512 + lane * 4;
    float4 v0 = ld_xb4(xb);
    float4 v1 = ld_xb4(xb + 128);
    float4 v2 = ld_xb4(xb + 256);
    float4 v3 = ld_xb4(xb + 384);
    float mx = c0 * v0.x + c1 * v1.x + c2 * v2.x + c3 * v3.x;
    float my = c0 * v0.y + c1 * v1.y + c2 * v2.y + c3 * v3.y;
    float mz = c0 * v0.z + c1 * v1.z + c2 * v2.z + c3 * v3.z;
    float mw = c0 * v0.w + c1 * v1.w + c2 * v2.w + c3 * v3.w;
    float* agg = (LAYER == 0) ? g_h1 : g_h2;
    float* p = agg + d * DIM + lane * 4;
    asm volatile("red.global.add.v4.f32 [%0], {%1,%2,%3,%4};"
                 :: "l"(p), "f"(mx), "f"(my), "f"(mz), "f"(mw) : "memory");
}

// ---------------- DistMult decoder ----------------
__global__ void __launch_bounds__(256) k_decode(const int* __restrict__ src,
                                                const int* __restrict__ dst,
                                                const int* __restrict__ et,
                                                const float* __restrict__ rel,
                                                float* __restrict__ out)
{
    int e = (blockIdx.x * blockDim.x + threadIdx.x) >> 5;
    int lane = threadIdx.x & 31;
    if (e >= NEDGE) return;
    int s = src[e], d = dst[e], t = et[e];
    float4 a = *(const float4*)&g_h2[(long long)s * DIM + lane * 4];
    float4 b = *(const float4*)&g_h2[(long long)d * DIM + lane * 4];
    float4 r = *(const float4*)&rel[t * DIM + lane * 4];
    float dot = a.x * r.x * b.x + a.y * r.y * b.y + a.z * r.z * b.z + a.w * r.w * b.w;
#pragma unroll
    for (int o = 16; o > 0; o >>= 1) dot += __shfl_xor_sync(0xffffffffu, dot, o);
    if (lane == 0) out[e] = dot;
}

__global__ void k_penalty(const float* __restrict__ rel, float* __restrict__ out, int idx)
{
    __shared__ float red[8];
    float s = 0.f;
    for (int i = threadIdx.x; i < R2 * DIM; i += 256) { float v = rel[i]; s += v * v; }
#pragma unroll
    for (int o = 16; o > 0; o >>= 1) s += __shfl_xor_sync(0xffffffffu, s, o);
    if ((threadIdx.x & 31) == 0) red[threadIdx.x >> 5] = s;
    __syncthreads();
    if (threadIdx.x < 8) {
        s = red[threadIdx.x];
#pragma unroll
        for (int o = 4; o > 0; o >>= 1) s += __shfl_xor_sync(0x000000ffu, s, o);
        if (threadIdx.x == 0) out[idx] = s;
    }
}

extern "C" void kernel_launch(void* const* d_in, const int* in_sizes, int n_in,
                              void* d_out, int out_size)
{
    const int* edge_index = (const int*)d_in[0];
    const int* src = edge_index;
    const int* dst = edge_index + NEDGE;
    const int* et  = (const int*)d_in[1];
    const float* emb    = (const float*)d_in[2];
    const float* ebias  = (const float*)d_in[3];
    const float* bases1 = (const float*)d_in[4];
    const float* comp1  = (const float*)d_in[5];
    const float* root1  = (const float*)d_in[6];
    const float* bias1  = (const float*)d_in[7];
    const float* bases2 = (const float*)d_in[8];
    const float* comp2  = (const float*)d_in[9];
    const float* root2  = (const float*)d_in[10];
    const float* bias2  = (const float*)d_in[11];
    const float* rel    = (const float*)d_in[12];
    float* out = (float*)d_out;

    static bool attr_done = false;
    if (!attr_done) {
        cudaFuncSetAttribute(k_gemm_mma<0>, cudaFuncAttributeMaxDynamicSharedMemorySize, 196608);
        cudaFuncSetAttribute(k_gemm_mma<1>, cudaFuncAttributeMaxDynamicSharedMemorySize, 196608);
        attr_done = true;
    }

    k_zero_counts<<<(N_ENT * R2 + 255) / 256, 256>>>();
    k_hist<<<(NEDGE + 255) / 256, 256>>>(dst, et);

    const int ngrid = (N_ENT + 127) / 128;   // 782

    k_build_wt<<<(WCOLS * DIM + 255) / 256, 256>>>(bases1, root1);
    k_gemm_mma<0><<<ngrid, 256, 196608>>>(emb, ebias, bias1);
    k_edge<0><<<NEDGE / 8, 256>>>(src, dst, et, comp1);

    k_build_wt<<<(WCOLS * DIM + 255) / 256, 256>>>(bases2, root2);
    k_gemm_mma<1><<<ngrid, 256, 196608>>>(emb, nullptr, bias2);
    k_edge<1><<<NEDGE / 8, 256>>>(src, dst, et, comp2);

    k_decode<<<NEDGE / 8, 256>>>(src, dst, et, rel, out);
    if (out_size > NEDGE)
        k_penalty<<<1, 256>>>(rel, out, out_size - 1);
}